// round 10
// baseline (speedup 1.0000x reference)
#include <cuda_runtime.h>

// Problem constants
#define BATCH 512
#define SEQ   1024
#define NTAG  50
#define TPAD  52          // padded tag count
#define BPB   4           // batches per block
#define NBLK  (BATCH / BPB)
#define NTHR  256         // 8 warps: w<4 fwd, w>=4 bwd; wid%4 = SMSP pairing
#define FULLM 0xffffffffu

// Scratch via __device__ globals (no allocs). Counter self-resets each run.
__device__ double g_partial[BATCH];
__device__ unsigned int g_done = 0;

// ----------------------------- f32x2 helpers --------------------------------
typedef unsigned long long u64;

__device__ __forceinline__ u64 pk2(float lo, float hi) {
    u64 r; asm("mov.b64 %0,{%1,%2};" : "=l"(r) : "f"(lo), "f"(hi)); return r;
}
__device__ __forceinline__ void upk2(float& lo, float& hi, u64 v) {
    asm("mov.b64 {%0,%1},%2;" : "=f"(lo), "=f"(hi) : "l"(v));
}
__device__ __forceinline__ u64 fma2_(u64 a, u64 b, u64 c) {
    u64 d; asm("fma.rn.f32x2 %0,%1,%2,%3;" : "=l"(d) : "l"(a), "l"(b), "l"(c)); return d;
}
__device__ __forceinline__ u64 mul2_(u64 a, u64 b) {
    u64 d; asm("mul.rn.f32x2 %0,%1,%2;" : "=l"(d) : "l"(a), "l"(b)); return d;
}
__device__ __forceinline__ u64 add2_(u64 a, u64 b) {
    u64 d; asm("add.rn.f32x2 %0,%1,%2;" : "=l"(d) : "l"(a), "l"(b)); return d;
}

// Accurate expf (one-time init paths): Cody-Waite + degree-7 Horner.
__device__ __forceinline__ float exp_acc(float x) {
    float n = rintf(x * 1.4426950408889634f);
    float r = fmaf(n, -0.693359375f, x);
    r = fmaf(n, 2.1219444005469057e-4f, r);
    float p = 1.9841270e-4f;
    p = fmaf(p, r, 1.3888889e-3f);
    p = fmaf(p, r, 8.3333333e-3f);
    p = fmaf(p, r, 4.1666668e-2f);
    p = fmaf(p, r, 1.6666667e-1f);
    p = fmaf(p, r, 0.5f);
    p = fmaf(p, r, 1.0f);
    p = fmaf(p, r, 1.0f);
    return p * __int_as_float(((int)n + 127) << 23);
}

// Cheap packed exp for per-step emissions (MUFU.EX2 path, ample accuracy margin).
__device__ __forceinline__ u64 pexpf2(u64 x2) {
    float x0, x1; upk2(x0, x1, x2);
    return pk2(__expf(x0), __expf(x1));
}

// Tags may be int32 (JAX w/o x64 silently downgrades int64) or genuine int64.
__device__ __forceinline__ int get_tag(const void* tags, int b, int t, int mode32) {
    if (mode32) return ((const int*)tags)[b * SEQ + t];
    return (int)((const long long*)tags)[b * SEQ + t];
}

__device__ __forceinline__ float warp_red_f(float v) {
    #pragma unroll
    for (int o = 16; o > 0; o >>= 1) v += __shfl_xor_sync(FULLM, v, o);
    return v;
}
__device__ __forceinline__ int warp_red_i(int v) {
    #pragma unroll
    for (int o = 16; o > 0; o >>= 1) v += __shfl_xor_sync(FULLM, v, o);
    return v;
}
__device__ __forceinline__ double warp_red_d(double v) {
    #pragma unroll
    for (int o = 16; o > 0; o >>= 1) v += __shfl_xor_sync(FULLM, v, o);
    return v;
}

// Forward/backward split, register-resident state exchanged via SHFL.IDX.
// Lane L owns outputs (2L, 2L+1) held as (alo, ahi); each step every lane
// broadcasts its pair with 2 shfls; 25 pairs x fma2 per output. No SMEM,
// no syncwarp in the loop. Exact pow2 renorm every 4 steps (pivot = lane0's
// lo value, i.e. a_0), exponent sums exact in int.
__global__ void __launch_bounds__(NTHR, 1) crf_main_kernel(
    const float* __restrict__ ts,          // [B,S,T] token_scores
    const void*  __restrict__ tags_raw,    // [B,S] int32 OR int64
    const int*   __restrict__ mask,        // [B,S] int32 (prefix mask)
    const float* __restrict__ trans,       // [T,T]
    const float* __restrict__ startt,      // [T]
    const float* __restrict__ endt,        // [T]
    float* __restrict__ out)               // [1]
{
    const int w    = threadIdx.x >> 5;
    const int lane = threadIdx.x & 31;
    const int bq   = w & 3;                 // batch slot in block
    const int dir  = w >> 2;                // 0 = fwd, 1 = bwd
    const int b    = blockIdx.x * BPB + bq;
    const int owner = (lane < 25);
    const int j0 = 2 * lane, j1 = j0 + 1;
    const int jc = owner ? j0 : 48;         // clamped column (keeps loads in-bounds)

    __shared__ float  afM[BPB][TPAD];       // final alpha_M
    __shared__ float  betaf[BPB][TPAD];     // final raw beta_M
    __shared__ float  num_sh[BPB];
    __shared__ int    sEb_sh[BPB];
    __shared__ double red_sh[NTHR];
    __shared__ unsigned int is_last;

    const float* tsb = ts   + (size_t)b * SEQ * NTAG;
    const int*   mkb = mask + (size_t)b * SEQ;

    // ---------------- sequence length (prefix mask) ----------------
    int ls = 0;
    for (int t = lane; t < SEQ; t += 32) ls += mkb[t];
    const int len = warp_red_i(ls);    // >= 1
    const int M   = len >> 1;          // meet point
    const int nb  = len - 1 - M;       // backward step count

    int sumEf = 0;                     // fwd exponent sum (fwd warps)

    if (dir == 0) {
        // =================== FORWARD WARP ===================
        // E column-pairs for owned outputs: E0[q]=(E[2q][j0],E[2q+1][j0]).
        u64 E0[25], E1[25];
        #pragma unroll
        for (int q = 0; q < 25; q++) {
            float e00 = 0.f, e01 = 0.f, e10 = 0.f, e11 = 0.f;
            if (owner) {
                int i0 = 2 * q, i1 = 2 * q + 1;
                e00 = exp_acc(__ldg(trans + i0 * NTAG + j0));
                e10 = exp_acc(__ldg(trans + i0 * NTAG + j1));
                e01 = exp_acc(__ldg(trans + i1 * NTAG + j0));
                e11 = exp_acc(__ldg(trans + i1 * NTAG + j1));
            }
            E0[q] = pk2(e00, e01);
            E1[q] = pk2(e10, e11);
        }

        // init alpha pair in registers
        float alo = 0.f, ahi = 0.f;
        if (owner) {
            alo = exp_acc(__ldg(startt + j0) + tsb[j0]);
            ahi = exp_acc(__ldg(startt + j1) + tsb[j1]);
        }

        const int lenf = M + 1;        // steps t = 1..M

        u64 xb[4];
        #pragma unroll
        for (int k = 0; k < 4; k++) {
            int t = 1 + k; if (t > SEQ - 1) t = SEQ - 1;
            xb[k] = __ldg((const u64*)(tsb + (size_t)t * NTAG + jc));
        }

        auto fstep = [&](u64 ex, bool renorm) {
            float plo = __shfl_sync(FULLM, alo, 0);
            float phi = __shfl_sync(FULLM, ahi, 0);
            if (renorm) {   // pivot = a_0 = plo; exact pow2 scaling via ex
                int eb = (__float_as_int(plo) >> 23) & 255;
                sumEf += eb - 127;
                float fac = __int_as_float((254 - eb) << 23);
                ex = mul2_(ex, pk2(fac, fac));
            }
            u64 pair0 = pk2(plo, phi);
            u64 a0a = fma2_(pair0, E0[0], 0ull);
            u64 a1a = fma2_(pair0, E1[0], 0ull);
            u64 a0b = 0ull, a1b = 0ull;
            #pragma unroll
            for (int q = 1; q < 25; q++) {
                float l = __shfl_sync(FULLM, alo, q);
                float h = __shfl_sync(FULLM, ahi, q);
                u64 p = pk2(l, h);
                if (q & 1) { a0b = fma2_(p, E0[q], a0b); a1b = fma2_(p, E1[q], a1b); }
                else       { a0a = fma2_(p, E0[q], a0a); a1a = fma2_(p, E1[q], a1a); }
            }
            u64 s0 = add2_(a0a, a0b), s1 = add2_(a1a, a1b);
            float p0, q0, p1, q1;
            upk2(p0, q0, s0); upk2(p1, q1, s1);
            u64 anew = mul2_(pk2(p0 + q0, p1 + q1), ex);
            upk2(alo, ahi, anew);
        };

        int tb = 1;
        for (; tb + 3 < lenf; tb += 4) {
            u64 xn[4];
            #pragma unroll
            for (int k = 0; k < 4; k++) {
                int t = tb + 4 + k; if (t > SEQ - 1) t = SEQ - 1;
                xn[k] = __ldg((const u64*)(tsb + (size_t)t * NTAG + jc));
            }
            fstep(pexpf2(xb[0]), true);    // t = tb ≡ 1 (mod 4)
            fstep(pexpf2(xb[1]), false);
            fstep(pexpf2(xb[2]), false);
            fstep(pexpf2(xb[3]), false);
            xb[0] = xn[0]; xb[1] = xn[1]; xb[2] = xn[2]; xb[3] = xn[3];
        }
        for (int t = tb; t < lenf; t++)
            fstep(pexpf2(xb[t - tb]), (t & 3) == 1);

        // publish alpha_M
        if (owner) { afM[bq][j0] = alo; afM[bq][j1] = ahi; }
    } else {
        // =================== BACKWARD WARP ===================
        int any_hi = 0;
        {
            const u64* p64 = (const u64*)tags_raw;
            #pragma unroll
            for (int i = 0; i < 16; i++) any_hi |= (int)(p64[i] >> 32);
        }
        const int mode32 = (any_hi != 0);

        // Numerator (gold-path score).
        float nsum = 0.f;
        for (int t = lane; t < len; t += 32) {
            int tg = get_tag(tags_raw, b, t, mode32);
            nsum += __ldg(tsb + t * NTAG + tg);
            if (t > 0) {
                int tp = get_tag(tags_raw, b, t - 1, mode32);
                nsum += __ldg(trans + tp * NTAG + tg);
            }
        }
        if (lane == 0)
            nsum += __ldg(startt + get_tag(tags_raw, b, 0, mode32))
                  + __ldg(endt   + get_tag(tags_raw, b, len - 1, mode32));
        nsum = warp_red_f(nsum);
        if (lane == 0) num_sh[bq] = nsum;

        int sumEb = 0;

        if (nb == 0) {
            if (owner) {
                betaf[bq][j0] = exp_acc(__ldg(endt + j0));
                betaf[bq][j1] = exp_acc(__ldg(endt + j1));
            }
        } else {
            // E row-pairs for owned outputs: ER0[q]=(E[j0][2q],E[j0][2q+1]).
            u64 ER0[25], ER1[25];
            #pragma unroll
            for (int q = 0; q < 25; q++) {
                float e00 = 0.f, e01 = 0.f, e10 = 0.f, e11 = 0.f;
                if (owner) {
                    int c0 = 2 * q, c1 = 2 * q + 1;
                    e00 = exp_acc(__ldg(trans + j0 * NTAG + c0));
                    e01 = exp_acc(__ldg(trans + j0 * NTAG + c1));
                    e10 = exp_acc(__ldg(trans + j1 * NTAG + c0));
                    e11 = exp_acc(__ldg(trans + j1 * NTAG + c1));
                }
                ER0[q] = pk2(e00, e01);
                ER1[q] = pk2(e10, e11);
            }

            // init c = exp(x_{len-1} + end) in registers
            float clo = 0.f, chi = 0.f;
            if (owner) {
                clo = exp_acc(tsb[(size_t)(len - 1) * NTAG + j0] + __ldg(endt + j0));
                chi = exp_acc(tsb[(size_t)(len - 1) * NTAG + j1] + __ldg(endt + j1));
            }

            const int nbm1 = nb - 1;   // normal steps; last step stores raw

            u64 xb[4];
            #pragma unroll
            for (int k = 0; k < 4; k++) {
                int t = len - 2 - k; if (t < 0) t = 0;
                xb[k] = __ldg((const u64*)(tsb + (size_t)t * NTAG + jc));
            }

            auto bstep = [&](u64 ex, bool renorm, bool fin) {
                float plo = __shfl_sync(FULLM, clo, 0);
                float phi = __shfl_sync(FULLM, chi, 0);
                if (renorm) {
                    int eb = (__float_as_int(plo) >> 23) & 255;
                    sumEb += eb - 127;
                    float fac = __int_as_float((254 - eb) << 23);
                    ex = mul2_(ex, pk2(fac, fac));
                }
                u64 pair0 = pk2(plo, phi);
                u64 a0a = fma2_(pair0, ER0[0], 0ull);
                u64 a1a = fma2_(pair0, ER1[0], 0ull);
                u64 a0b = 0ull, a1b = 0ull;
                #pragma unroll
                for (int q = 1; q < 25; q++) {
                    float l = __shfl_sync(FULLM, clo, q);
                    float h = __shfl_sync(FULLM, chi, q);
                    u64 p = pk2(l, h);
                    if (q & 1) { a0b = fma2_(p, ER0[q], a0b); a1b = fma2_(p, ER1[q], a1b); }
                    else       { a0a = fma2_(p, ER0[q], a0a); a1a = fma2_(p, ER1[q], a1a); }
                }
                u64 s0 = add2_(a0a, a0b), s1 = add2_(a1a, a1b);
                float p0, q0, p1, q1;
                upk2(p0, q0, s0); upk2(p1, q1, s1);
                if (fin) {
                    if (owner) {
                        betaf[bq][j0] = p0 + q0;
                        betaf[bq][j1] = p1 + q1;
                    }
                } else {
                    u64 cnew = mul2_(pk2(p0 + q0, p1 + q1), ex);
                    upk2(clo, chi, cnew);
                }
            };

            int idx = 0;
            for (; idx + 3 < nbm1; idx += 4) {
                u64 xn[4];
                #pragma unroll
                for (int k = 0; k < 4; k++) {
                    int t = len - 2 - (idx + 4 + k); if (t < 0) t = 0;
                    xn[k] = __ldg((const u64*)(tsb + (size_t)t * NTAG + jc));
                }
                bstep(pexpf2(xb[0]), true, false);
                bstep(pexpf2(xb[1]), false, false);
                bstep(pexpf2(xb[2]), false, false);
                bstep(pexpf2(xb[3]), false, false);
                xb[0] = xn[0]; xb[1] = xn[1]; xb[2] = xn[2]; xb[3] = xn[3];
            }
            for (int k = 0; idx < nbm1; idx++, k++)
                bstep(pexpf2(xb[k]), (idx & 3) == 0, false);

            bstep(0ull, false, true);      // final: store raw beta_M
        }

        if (lane == 0) sEb_sh[bq] = sumEb;
    }

    // ---------------- combine: den = ln2*(sEf+sEb) + log(sum alpha*beta) ----
    __syncthreads();
    if (dir == 0) {
        double part = 0.0;
        if (owner) {
            part = (double)afM[bq][j0] * (double)betaf[bq][j0]
                 + (double)afM[bq][j1] * (double)betaf[bq][j1];
        }
        part = warp_red_d(part);
        if (lane == 0) {
            double den = (double)(sumEf + sEb_sh[bq]) * 0.6931471805599453
                       + log(part);
            g_partial[b] = den - (double)num_sh[bq];
        }
    }

    // ---------------- last-block final reduction (deterministic) ----------
    __syncthreads();
    __threadfence();
    if (threadIdx.x == 0)
        is_last = (atomicAdd(&g_done, 1u) == (unsigned)(NBLK - 1));
    __syncthreads();
    if (is_last) {
        const int tid = threadIdx.x;           // 256 threads, 512 partials
        double s = g_partial[tid] + g_partial[tid + NTHR];
        red_sh[tid] = s;
        __syncthreads();
        #pragma unroll
        for (int o = 128; o > 0; o >>= 1) {
            if (tid < o) red_sh[tid] += red_sh[tid + o];
            __syncthreads();
        }
        if (tid == 0) {
            out[0] = (float)(red_sh[0] * (1.0 / (double)BATCH));
            g_done = 0;                        // reset for next graph replay
        }
    }
}

extern "C" void kernel_launch(void* const* d_in, const int* in_sizes, int n_in,
                              void* d_out, int out_size)
{
    const float* token_scores = (const float*)d_in[0];
    const void*  tags         = (const void*)d_in[1];
    const int*   token_mask   = (const int*)d_in[2];
    const float* transitions  = (const float*)d_in[3];
    const float* start_trans  = (const float*)d_in[4];
    const float* end_trans    = (const float*)d_in[5];
    float* out = (float*)d_out;

    crf_main_kernel<<<NBLK, NTHR>>>(token_scores, tags, token_mask,
                                    transitions, start_trans, end_trans, out);
}

// round 11
// speedup vs baseline: 1.5232x; 1.5232x over previous
#include <cuda_runtime.h>

// Problem constants
#define BATCH 512
#define SEQ   1024
#define NTAG  50
#define TPAD  52          // padded tag count (multiple of 4)
#define BPB   4           // batches per block
#define NBLK  (BATCH / BPB)
#define NTHR  256         // 8 warps: w<4 fwd, w>=4 bwd; wid%4 = SMSP pairing
#define FULLM 0xffffffffu

// Scratch via __device__ globals (no allocs). Counter self-resets each run.
__device__ double g_partial[BATCH];
__device__ int    g_len[BATCH];
__device__ int    g_sched[BATCH];
__device__ unsigned int g_done = 0;

// ----------------------------- f32x2 helpers --------------------------------
typedef unsigned long long u64;

__device__ __forceinline__ u64 pk2(float lo, float hi) {
    u64 r; asm("mov.b64 %0,{%1,%2};" : "=l"(r) : "f"(lo), "f"(hi)); return r;
}
__device__ __forceinline__ void upk2(float& lo, float& hi, u64 v) {
    asm("mov.b64 {%0,%1},%2;" : "=f"(lo), "=f"(hi) : "l"(v));
}
__device__ __forceinline__ u64 fma2_(u64 a, u64 b, u64 c) {
    u64 d; asm("fma.rn.f32x2 %0,%1,%2,%3;" : "=l"(d) : "l"(a), "l"(b), "l"(c)); return d;
}
__device__ __forceinline__ u64 mul2_(u64 a, u64 b) {
    u64 d; asm("mul.rn.f32x2 %0,%1,%2;" : "=l"(d) : "l"(a), "l"(b)); return d;
}
__device__ __forceinline__ u64 add2_(u64 a, u64 b) {
    u64 d; asm("add.rn.f32x2 %0,%1,%2;" : "=l"(d) : "l"(a), "l"(b)); return d;
}

// Accurate expf (one-time init paths): Cody-Waite + degree-7 Horner.
__device__ __forceinline__ float exp_acc(float x) {
    float n = rintf(x * 1.4426950408889634f);
    float r = fmaf(n, -0.693359375f, x);
    r = fmaf(n, 2.1219444005469057e-4f, r);
    float p = 1.9841270e-4f;
    p = fmaf(p, r, 1.3888889e-3f);
    p = fmaf(p, r, 8.3333333e-3f);
    p = fmaf(p, r, 4.1666668e-2f);
    p = fmaf(p, r, 1.6666667e-1f);
    p = fmaf(p, r, 0.5f);
    p = fmaf(p, r, 1.0f);
    p = fmaf(p, r, 1.0f);
    return p * __int_as_float(((int)n + 127) << 23);
}

// Cheap packed exp for per-step emissions (MUFU.EX2 path, ample accuracy margin).
__device__ __forceinline__ u64 pexpf2(u64 x2) {
    float x0, x1; upk2(x0, x1, x2);
    return pk2(__expf(x0), __expf(x1));
}

// Tags may be int32 (JAX w/o x64 silently downgrades int64) or genuine int64.
__device__ __forceinline__ int get_tag(const void* tags, int b, int t, int mode32) {
    if (mode32) return ((const int*)tags)[b * SEQ + t];
    return (int)((const long long*)tags)[b * SEQ + t];
}

__device__ __forceinline__ float warp_red_f(float v) {
    #pragma unroll
    for (int o = 16; o > 0; o >>= 1) v += __shfl_xor_sync(FULLM, v, o);
    return v;
}
__device__ __forceinline__ int warp_red_i(int v) {
    #pragma unroll
    for (int o = 16; o > 0; o >>= 1) v += __shfl_xor_sync(FULLM, v, o);
    return v;
}
__device__ __forceinline__ double warp_red_d(double v) {
    #pragma unroll
    for (int o = 16; o > 0; o >>= 1) v += __shfl_xor_sync(FULLM, v, o);
    return v;
}

// ---------------- prologue kernel 1: per-batch lengths ----------------
__global__ void crf_len_kernel(const int* __restrict__ mask) {
    const int b = blockIdx.x, lane = threadIdx.x;
    int s = 0;
    for (int t = lane; t < SEQ; t += 32) s += mask[b * SEQ + t];
    s = warp_red_i(s);
    if (lane == 0) g_len[b] = s;
}

// ---------------- prologue kernel 2: sort + long/short pairing ----------
// Bitonic sort of 512 (len,batch) keys. Rank r is paired with rank 511-r so
// every SMSP ends up with one long and one short chain. Deterministic
// (tie-break by batch id inside the key).
__global__ void crf_sched_kernel() {
    __shared__ int keys[BATCH];
    const int tid = threadIdx.x;
    keys[tid] = g_len[tid] * 1024 + tid;
    __syncthreads();
    for (int k = 2; k <= BATCH; k <<= 1) {
        for (int j = k >> 1; j > 0; j >>= 1) {
            int ixj = tid ^ j;
            if (ixj > tid) {
                int a = keys[tid], c = keys[ixj];
                bool up = ((tid & k) == 0);
                if (up ? (a < c) : (a > c)) { keys[tid] = c; keys[ixj] = a; }
            }
            __syncthreads();
        }
    }
    // rank tid -> (block k2, slot q): slots 0/2 take ranks 2k,2k+1;
    // slots 1/3 take ranks 511-2k,510-2k (the opposite extreme).
    const int batch = keys[tid] & 1023;
    int k2, q;
    if (tid < 256)       { k2 = tid >> 1;         q = (tid & 1) ? 2 : 0; }
    else if (tid & 1)    { k2 = (511 - tid) >> 1; q = 1; }
    else                 { k2 = (510 - tid) >> 1; q = 3; }
    g_sched[k2 * 4 + q] = batch;
}

// Forward/backward split: den = log sum_i alpha_M[i] * beta_M[i].
// fwd warps (w<4) handle slot w; bwd warps (w>=4) handle slot perm[w-4],
// perm = (1,0,3,2)  =>  each SMSP gets fwd(long)+bwd(short) or vice versa.
// Scaled-linear domain, exact pow2 renorm every 4 steps, emission prefetch 8.
__global__ void __launch_bounds__(NTHR, 1) crf_main_kernel(
    const float* __restrict__ ts,          // [B,S,T] token_scores
    const void*  __restrict__ tags_raw,    // [B,S] int32 OR int64
    const int*   __restrict__ mask,        // [B,S] int32 (prefix mask)
    const float* __restrict__ trans,       // [T,T]
    const float* __restrict__ startt,      // [T]
    const float* __restrict__ endt,        // [T]
    float* __restrict__ out)               // [1]
{
    const int w    = threadIdx.x >> 5;
    const int lane = threadIdx.x & 31;
    const int dir  = w >> 2;                // 0 = fwd, 1 = bwd
    const int bperm[4] = {1, 0, 3, 2};
    const int bq   = (dir == 0) ? (w & 3) : bperm[w & 3];   // slot in block
    const int b    = g_sched[blockIdx.x * BPB + bq];        // scheduled batch
    const int owner = (lane < 25);
    const int j0 = 2 * lane, j1 = 2 * lane + 1;

    __shared__ __align__(16) float afb[BPB][2][TPAD];   // fwd alpha buffers
    __shared__ __align__(16) float cbb[BPB][2][TPAD];   // bwd c buffers
    __shared__ float  betaf[BPB][TPAD];                 // final raw beta_M
    __shared__ float  num_sh[BPB];
    __shared__ int    sEb_sh[BPB];
    __shared__ double red_sh[NTHR];
    __shared__ unsigned int is_last;

    const float* tsb = ts + (size_t)b * SEQ * NTAG;

    const int len = g_len[b];          // >= 1
    const int M   = len >> 1;          // meet point
    const int nb  = len - 1 - M;       // backward step count

    int sumEf = 0, curf = 0;           // fwd state (live only in fwd warps)

    if (dir == 0) {
        // =================== FORWARD WARP ===================
        u64 E0[26], E1[26];
        #pragma unroll
        for (int q = 0; q < 26; q++) {
            float e00 = 0.f, e01 = 0.f, e10 = 0.f, e11 = 0.f;
            if (owner) {
                int i0 = 2 * q, i1 = 2 * q + 1;
                if (i0 < NTAG) {
                    e00 = exp_acc(__ldg(trans + i0 * NTAG + j0));
                    e10 = exp_acc(__ldg(trans + i0 * NTAG + j1));
                }
                if (i1 < NTAG) {
                    e01 = exp_acc(__ldg(trans + i1 * NTAG + j0));
                    e11 = exp_acc(__ldg(trans + i1 * NTAG + j1));
                }
            }
            E0[q] = pk2(e00, e01);
            E1[q] = pk2(e10, e11);
        }

        float* a0f = afb[bq][0];
        float* a1f = afb[bq][1];
        if (owner) {
            a0f[j0] = exp_acc(__ldg(startt + j0) + tsb[j0]);
            a0f[j1] = exp_acc(__ldg(startt + j1) + tsb[j1]);
        }
        if (lane == 25) {
            a0f[50] = 0.f; a0f[51] = 0.f; a1f[50] = 0.f; a1f[51] = 0.f;
        }
        __syncwarp();

        const int lenf = M + 1;        // steps t = 1..M

        u64 xb[8];
        #pragma unroll
        for (int k = 0; k < 8; k++) {
            int t = 1 + k; if (t > SEQ - 1) t = SEQ - 1;
            xb[k] = owner ? __ldg((const u64*)(tsb + (size_t)t * NTAG + j0)) : 0ull;
        }

        auto fstep = [&](u64 ex, bool renorm) {
            const float* af = afb[bq][curf];
            const ulonglong2* av = (const ulonglong2*)af;
            float* an = afb[bq][curf ^ 1];
            if (renorm) {
                int eb = (__float_as_int(af[0]) >> 23) & 255;
                sumEf += eb - 127;
                float fac = __int_as_float((254 - eb) << 23);   // 2^{-e}, exact
                ex = mul2_(ex, pk2(fac, fac));
            }
            u64 c0[4] = {0,0,0,0}, c1[4] = {0,0,0,0};
            #pragma unroll
            for (int q = 0; q < 13; q++) {
                ulonglong2 v = av[q];
                c0[0] = fma2_(v.x, E0[2 * q],     c0[0]);
                c0[q & 1 ? 3 : 1] = fma2_(v.y, E0[2 * q + 1], c0[q & 1 ? 3 : 1]);
                c1[0] = fma2_(v.x, E1[2 * q],     c1[0]);
                c1[q & 1 ? 3 : 1] = fma2_(v.y, E1[2 * q + 1], c1[q & 1 ? 3 : 1]);
            }
            u64 s0 = add2_(add2_(c0[0], c0[1]), c0[3]);
            u64 s1 = add2_(add2_(c1[0], c1[1]), c1[3]);
            float p0, q0, p1, q1;
            upk2(p0, q0, s0); upk2(p1, q1, s1);
            u64 anew = mul2_(pk2(p0 + q0, p1 + q1), ex);
            if (owner) *(u64*)(an + j0) = anew;
            curf ^= 1;
            __syncwarp();
        };

        int tb = 1;
        for (; tb + 7 < lenf; tb += 8) {
            u64 xn[8];
            #pragma unroll
            for (int k = 0; k < 8; k++) {
                int t = tb + 8 + k; if (t > SEQ - 1) t = SEQ - 1;
                xn[k] = owner ? __ldg((const u64*)(tsb + (size_t)t * NTAG + j0)) : 0ull;
            }
            #pragma unroll
            for (int k = 0; k < 8; k++)
                fstep(pexpf2(xb[k]), (k & 3) == 0);
            #pragma unroll
            for (int k = 0; k < 8; k++) xb[k] = xn[k];
        }
        for (int t = tb; t < lenf; t++)
            fstep(pexpf2(xb[t - tb]), (t & 3) == 1);
    } else {
        // =================== BACKWARD WARP ===================
        int any_hi = 0;
        {
            const u64* p64 = (const u64*)tags_raw;
            #pragma unroll
            for (int i = 0; i < 16; i++) any_hi |= (int)(p64[i] >> 32);
        }
        const int mode32 = (any_hi != 0);

        // Numerator (gold-path score).
        float nsum = 0.f;
        for (int t = lane; t < len; t += 32) {
            int tg = get_tag(tags_raw, b, t, mode32);
            nsum += __ldg(tsb + t * NTAG + tg);
            if (t > 0) {
                int tp = get_tag(tags_raw, b, t - 1, mode32);
                nsum += __ldg(trans + tp * NTAG + tg);
            }
        }
        if (lane == 0)
            nsum += __ldg(startt + get_tag(tags_raw, b, 0, mode32))
                  + __ldg(endt   + get_tag(tags_raw, b, len - 1, mode32));
        nsum = warp_red_f(nsum);
        if (lane == 0) num_sh[bq] = nsum;

        int sumEb = 0;

        if (nb == 0) {
            if (owner) {
                betaf[bq][j0] = exp_acc(__ldg(endt + j0));
                betaf[bq][j1] = exp_acc(__ldg(endt + j1));
            }
        } else {
            u64 ER0[26], ER1[26];
            #pragma unroll
            for (int q = 0; q < 26; q++) {
                float e00 = 0.f, e01 = 0.f, e10 = 0.f, e11 = 0.f;
                if (owner) {
                    int c0 = 2 * q, c1 = 2 * q + 1;
                    if (c0 < NTAG) {
                        e00 = exp_acc(__ldg(trans + j0 * NTAG + c0));
                        e10 = exp_acc(__ldg(trans + j1 * NTAG + c0));
                    }
                    if (c1 < NTAG) {
                        e01 = exp_acc(__ldg(trans + j0 * NTAG + c1));
                        e11 = exp_acc(__ldg(trans + j1 * NTAG + c1));
                    }
                }
                ER0[q] = pk2(e00, e01);
                ER1[q] = pk2(e10, e11);
            }

            float* c0f = cbb[bq][0];
            float* c1f = cbb[bq][1];
            if (owner) {   // c_j = exp(x_{len-1}[j] + end_j)
                c0f[j0] = exp_acc(tsb[(size_t)(len - 1) * NTAG + j0] + __ldg(endt + j0));
                c0f[j1] = exp_acc(tsb[(size_t)(len - 1) * NTAG + j1] + __ldg(endt + j1));
            }
            if (lane == 25) {
                c0f[50] = 0.f; c0f[51] = 0.f; c1f[50] = 0.f; c1f[51] = 0.f;
            }
            __syncwarp();

            int curb = 0;
            const int nbm1 = nb - 1;   // normal steps; last step stores raw

            u64 xb[8];
            #pragma unroll
            for (int k = 0; k < 8; k++) {
                int t = len - 2 - k; if (t < 0) t = 0;
                xb[k] = owner ? __ldg((const u64*)(tsb + (size_t)t * NTAG + j0)) : 0ull;
            }

            auto bstep = [&](u64 ex, bool renorm, bool fin) {
                const float* cf = cbb[bq][curb];
                const ulonglong2* cv = (const ulonglong2*)cf;
                float* cn = cbb[bq][curb ^ 1];
                if (renorm) {
                    int eb = (__float_as_int(cf[0]) >> 23) & 255;
                    sumEb += eb - 127;
                    float fac = __int_as_float((254 - eb) << 23);
                    ex = mul2_(ex, pk2(fac, fac));
                }
                u64 c0[4] = {0,0,0,0}, c1[4] = {0,0,0,0};
                #pragma unroll
                for (int q = 0; q < 13; q++) {
                    ulonglong2 v = cv[q];
                    c0[0] = fma2_(v.x, ER0[2 * q],     c0[0]);
                    c0[q & 1 ? 3 : 1] = fma2_(v.y, ER0[2 * q + 1], c0[q & 1 ? 3 : 1]);
                    c1[0] = fma2_(v.x, ER1[2 * q],     c1[0]);
                    c1[q & 1 ? 3 : 1] = fma2_(v.y, ER1[2 * q + 1], c1[q & 1 ? 3 : 1]);
                }
                u64 s0 = add2_(add2_(c0[0], c0[1]), c0[3]);
                u64 s1 = add2_(add2_(c1[0], c1[1]), c1[3]);
                float p0, q0, p1, q1;
                upk2(p0, q0, s0); upk2(p1, q1, s1);
                if (fin) {
                    if (owner) {
                        betaf[bq][j0] = p0 + q0;
                        betaf[bq][j1] = p1 + q1;
                    }
                } else {
                    u64 cnew = mul2_(pk2(p0 + q0, p1 + q1), ex);
                    if (owner) *(u64*)(cn + j0) = cnew;
                }
                curb ^= 1;
                __syncwarp();
            };

            int idx = 0;
            for (; idx + 7 < nbm1; idx += 8) {
                u64 xn[8];
                #pragma unroll
                for (int k = 0; k < 8; k++) {
                    int t = len - 2 - (idx + 8 + k); if (t < 0) t = 0;
                    xn[k] = owner ? __ldg((const u64*)(tsb + (size_t)t * NTAG + j0)) : 0ull;
                }
                #pragma unroll
                for (int k = 0; k < 8; k++)
                    bstep(pexpf2(xb[k]), (k & 3) == 0, false);
                #pragma unroll
                for (int k = 0; k < 8; k++) xb[k] = xn[k];
            }
            for (int k = 0; idx < nbm1; idx++, k++)
                bstep(pexpf2(xb[k]), (idx & 3) == 0, false);

            bstep(0ull, false, true);      // final: store raw beta_M
        }

        if (lane == 0) sEb_sh[bq] = sumEb;
    }

    // ---------------- combine: den = ln2*(sEf+sEb) + log(sum alpha*beta) ----
    __syncthreads();
    if (dir == 0) {
        double part = 0.0;
        if (owner) {
            const float* af = afb[bq][curf];
            part = (double)af[j0] * (double)betaf[bq][j0]
                 + (double)af[j1] * (double)betaf[bq][j1];
        }
        part = warp_red_d(part);
        if (lane == 0) {
            double den = (double)(sumEf + sEb_sh[bq]) * 0.6931471805599453
                       + log(part);
            g_partial[b] = den - (double)num_sh[bq];
        }
    }

    // ---------------- last-block final reduction (deterministic) ----------
    __syncthreads();
    __threadfence();
    if (threadIdx.x == 0)
        is_last = (atomicAdd(&g_done, 1u) == (unsigned)(NBLK - 1));
    __syncthreads();
    if (is_last) {
        const int tid = threadIdx.x;           // 256 threads, 512 partials
        double s = g_partial[tid] + g_partial[tid + NTHR];
        red_sh[tid] = s;
        __syncthreads();
        #pragma unroll
        for (int o = 128; o > 0; o >>= 1) {
            if (tid < o) red_sh[tid] += red_sh[tid + o];
            __syncthreads();
        }
        if (tid == 0) {
            out[0] = (float)(red_sh[0] * (1.0 / (double)BATCH));
            g_done = 0;                        // reset for next graph replay
        }
    }
}

extern "C" void kernel_launch(void* const* d_in, const int* in_sizes, int n_in,
                              void* d_out, int out_size)
{
    const float* token_scores = (const float*)d_in[0];
    const void*  tags         = (const void*)d_in[1];
    const int*   token_mask   = (const int*)d_in[2];
    const float* transitions  = (const float*)d_in[3];
    const float* start_trans  = (const float*)d_in[4];
    const float* end_trans    = (const float*)d_in[5];
    float* out = (float*)d_out;

    crf_len_kernel<<<BATCH, 32>>>(token_mask);
    crf_sched_kernel<<<1, BATCH>>>();
    crf_main_kernel<<<NBLK, NTHR>>>(token_scores, tags, token_mask,
                                    transitions, start_trans, end_trans, out);
}